// round 15
// baseline (speedup 1.0000x reference)
#include <cuda_runtime.h>
#include <cuda_bf16.h>
#include <stdint.h>
#include <math.h>

#define SQ   64
#define BA   64
#define HID  1024
#define EMBD 1024
#define VOC  10000
#define BH   (BA*HID)
#define MROWS (SQ*BA)   // 4096
#define K3   (3*HID)    // 3072 split-bf16 K

#define NCTA 128
#define RKS  384        // layer0 k3 per slice (3072/8)
#define RKS2 768        // layer1 k6144 per slice (6144/8)
#define RPAD 392        // padded smem row stride (halves)
#define RTHREADS 512

// ---- scratch (device globals) ----
__device__ float g_P0[MROWS*HID];
__device__ float g_part0[8*BA*HID];
__device__ float g_part1[8*BA*HID];
__device__ float g_Hlast0[BH];
__device__ float g_Hlast1[BH];

__device__ __nv_bfloat16 g_A3  [MROWS*K3];      // packed A for K1 (emb gather)
__device__ __nv_bfloat16 g_W03 [HID*K3];        // packed weights (B-order hi|lo|hi)
__device__ __nv_bfloat16 g_W13 [HID*K3];
__device__ __nv_bfloat16 g_Wd3 [VOC*K3];
__device__ __nv_bfloat16 g_Wh03[HID*K3];
__device__ __nv_bfloat16 g_Wh13[HID*K3];
__device__ __nv_bfloat16 g_Hp0 [(SQ+1)*BA*K3];  // packed hidden chains (A-order)
__device__ __nv_bfloat16 g_Hp1 [(SQ+1)*BA*K3];

// ---- hierarchical grid barrier (monotone counters, wrap-safe) ----
__device__ unsigned g_leaf[8 * 32];
__device__ unsigned g_root;
__device__ volatile unsigned g_gen;

__device__ __forceinline__ void gbar()
{
    __syncthreads();
    if (threadIdx.x == 0) {
        __threadfence();
        unsigned my = g_gen;
        const int leaf = (blockIdx.x & 7) * 32;
        if ((atomicAdd(&g_leaf[leaf], 1u) & 15u) == 15u) {
            if ((atomicAdd(&g_root, 1u) & 7u) == 7u) {
                __threadfence();
                g_gen = my + 1;
            }
        }
        while (g_gen == my) { }
        __threadfence();
    }
    __syncthreads();
}

// ---------------------------------------------------------------------------
// Split-pack: fp32 [R,HID] -> bf16 [R,3*HID].
// A-order (AORD=1): [hi|hi|lo].  B-order (AORD=0): [hi|lo|hi].
// ---------------------------------------------------------------------------
template<bool GATHER, bool AORD>
__global__ __launch_bounds__(256)
void pack_split(const float* __restrict__ src, const int* __restrict__ idx,
                __nv_bfloat16* __restrict__ dst, int R)
{
    long i = (long)blockIdx.x * 256 + threadIdx.x;
    if (i >= (long)R * (HID / 4)) return;
    int r  = (int)(i / (HID / 4));
    int k4 = (int)(i % (HID / 4)) * 4;
    const float* row = GATHER ? (src + (size_t)idx[r] * HID)
                              : (src + (size_t)r * HID);
    float4 v = *(const float4*)(row + k4);

    __nv_bfloat16 h[4], l[4];
    float f[4] = {v.x, v.y, v.z, v.w};
    #pragma unroll
    for (int j = 0; j < 4; j++) {
        h[j] = __float2bfloat16(f[j]);
        l[j] = __float2bfloat16(f[j] - __bfloat162float(h[j]));
    }
    __nv_bfloat16* d = dst + (size_t)r * K3;
    *(uint2*)(d + k4)                        = *(uint2*)h;
    *(uint2*)(d + (AORD ? HID : 2*HID) + k4) = *(uint2*)h;
    *(uint2*)(d + (AORD ? 2*HID : HID) + k4) = *(uint2*)l;
}

__device__ __forceinline__ void mma16816(float* c, const uint32_t* a, const uint32_t* b)
{
    asm volatile(
        "mma.sync.aligned.m16n8k16.row.col.f32.bf16.bf16.f32 "
        "{%0,%1,%2,%3}, {%4,%5,%6,%7}, {%8,%9}, {%0,%1,%2,%3};"
        : "+f"(c[0]), "+f"(c[1]), "+f"(c[2]), "+f"(c[3])
        : "r"(a[0]), "r"(a[1]), "r"(a[2]), "r"(a[3]), "r"(b[0]), "r"(b[1]));
}

// ---------------------------------------------------------------------------
// bf16 tensor-core GEMM (mma.sync): C = A[M,K3] @ B[N,K3]^T (+bias)
// ---------------------------------------------------------------------------
#define SMP 40

template<bool BIAS, bool GUARD>
__global__ __launch_bounds__(256, 2)
void gemm_bf16(const __nv_bfloat16* __restrict__ A, const __nv_bfloat16* __restrict__ B,
               const float* __restrict__ bias, float* __restrict__ C, int N)
{
    __shared__ __nv_bfloat16 As[2][128 * SMP];
    __shared__ __nv_bfloat16 Bs[2][128 * SMP];

    const int t    = threadIdx.x;
    const int warp = t >> 5, lane = t & 31;
    const int mBase = blockIdx.x * 128;
    const int nBase = blockIdx.y * 128;
    const int warpM = (warp >> 1) * 32;
    const int warpN = (warp & 1) * 64;

    const int lr = t >> 1;
    const int lk = (t & 1) * 16;

    const __nv_bfloat16* Ag = A + (size_t)(mBase + lr) * K3 + lk;
    int gn = nBase + lr;
    bool bvalid = true;
    if (GUARD && gn >= N) { bvalid = false; gn = N - 1; }
    const __nv_bfloat16* Bg = B + (size_t)gn * K3 + lk;

    uint4 av0 = *(const uint4*)(Ag);
    uint4 av1 = *(const uint4*)(Ag + 8);
    uint4 bv0 = make_uint4(0,0,0,0), bv1 = make_uint4(0,0,0,0);
    if (!GUARD || bvalid) { bv0 = *(const uint4*)(Bg); bv1 = *(const uint4*)(Bg + 8); }

    float acc[2][8][4];
    #pragma unroll
    for (int mi = 0; mi < 2; mi++)
        #pragma unroll
        for (int ni = 0; ni < 8; ni++)
            #pragma unroll
            for (int j = 0; j < 4; j++) acc[mi][ni][j] = 0.f;

    int buf = 0;
    for (int kt = 0; kt < K3; kt += 32) {
        *(uint4*)&As[buf][lr * SMP + lk]     = av0;
        *(uint4*)&As[buf][lr * SMP + lk + 8] = av1;
        *(uint4*)&Bs[buf][lr * SMP + lk]     = bv0;
        *(uint4*)&Bs[buf][lr * SMP + lk + 8] = bv1;
        __syncthreads();

        if (kt + 32 < K3) {
            av0 = *(const uint4*)(Ag + kt + 32);
            av1 = *(const uint4*)(Ag + kt + 40);
            if (!GUARD || bvalid) {
                bv0 = *(const uint4*)(Bg + kt + 32);
                bv1 = *(const uint4*)(Bg + kt + 40);
            }
        }

        #pragma unroll
        for (int ks = 0; ks < 2; ks++) {
            const int kk = ks * 16 + (lane & 3) * 2;
            uint32_t a[2][4], b[8][2];
            #pragma unroll
            for (int mi = 0; mi < 2; mi++) {
                int r0 = warpM + mi * 16 + (lane >> 2);
                a[mi][0] = *(const uint32_t*)&As[buf][ r0      * SMP + kk];
                a[mi][1] = *(const uint32_t*)&As[buf][(r0 + 8) * SMP + kk];
                a[mi][2] = *(const uint32_t*)&As[buf][ r0      * SMP + kk + 8];
                a[mi][3] = *(const uint32_t*)&As[buf][(r0 + 8) * SMP + kk + 8];
            }
            #pragma unroll
            for (int ni = 0; ni < 8; ni++) {
                int n0 = warpN + ni * 8 + (lane >> 2);
                b[ni][0] = *(const uint32_t*)&Bs[buf][n0 * SMP + kk];
                b[ni][1] = *(const uint32_t*)&Bs[buf][n0 * SMP + kk + 8];
            }
            #pragma unroll
            for (int mi = 0; mi < 2; mi++)
                #pragma unroll
                for (int ni = 0; ni < 8; ni++)
                    mma16816(acc[mi][ni], a[mi], b[ni]);
        }
        buf ^= 1;
    }

    #pragma unroll
    for (int mi = 0; mi < 2; mi++) {
        int row = mBase + warpM + mi * 16 + (lane >> 2);
        #pragma unroll
        for (int ni = 0; ni < 8; ni++) {
            int col = nBase + warpN + ni * 8 + (lane & 3) * 2;
            if (!GUARD || col < N) {
                float bb0 = BIAS ? bias[col]     : 0.f;
                float bb1 = BIAS ? bias[col + 1] : 0.f;
                *(float2*)(C + (size_t)row * N + col) =
                    make_float2(acc[mi][ni][0] + bb0, acc[mi][ni][1] + bb1);
                *(float2*)(C + (size_t)(row + 8) * N + col) =
                    make_float2(acc[mi][ni][2] + bb0, acc[mi][ni][3] + bb1);
            }
        }
    }
}

// ---------------------------------------------------------------------------
// Fused 2-layer wavefront recurrence, 512 threads (16 warps = 4/SMSP).
// 128 CTAs = 8 k-slices x 16 col-groups.
// Wave w: layer0 step w (if w<SQ) + layer1 step w-1 (if w>=1).
// Warp layout: mt = warp&3 (m16 tile of 64 rows), nh = warp>>2 (16-col strip).
// ---------------------------------------------------------------------------
__device__ __forceinline__ void mma_block512(const __nv_bfloat16* As, const __nv_bfloat16* Bs,
                                             int arow, int kq, int crow, float acc[2][4])
{
    #pragma unroll 4
    for (int k = 0; k < RKS; k += 16) {
        uint32_t a[4];
        a[0] = *(const uint32_t*)(As + (size_t) arow      * RPAD + k + kq);
        a[1] = *(const uint32_t*)(As + (size_t)(arow + 8) * RPAD + k + kq);
        a[2] = *(const uint32_t*)(As + (size_t) arow      * RPAD + k + kq + 8);
        a[3] = *(const uint32_t*)(As + (size_t)(arow + 8) * RPAD + k + kq + 8);
        #pragma unroll
        for (int nt = 0; nt < 2; nt++) {
            int c = crow + nt * 8;
            uint32_t b[2];
            b[0] = *(const uint32_t*)(Bs + (size_t)c * RPAD + k + kq);
            b[1] = *(const uint32_t*)(Bs + (size_t)c * RPAD + k + kq + 8);
            mma16816(acc[nt], a, b);
        }
    }
}

__global__ __launch_bounds__(RTHREADS, 1)
void rnn_fused(const __nv_bfloat16* __restrict__ Wh0p,
               const __nv_bfloat16* __restrict__ W1p,
               const __nv_bfloat16* __restrict__ Wh1p,
               const float* __restrict__ P0,
               const float* __restrict__ bias0,
               const float* __restrict__ bias1,
               __nv_bfloat16* __restrict__ Hp0,
               __nv_bfloat16* __restrict__ Hp1,
               float* __restrict__ Hl0,
               float* __restrict__ Hl1)
{
    extern __shared__ __nv_bfloat16 smh[];
    __nv_bfloat16* B0s = smh;                    // layer0 weight slice
    __nv_bfloat16* B1a = smh + 64 * RPAD;        // layer1 weight chunk 0
    __nv_bfloat16* B1b = smh + 2 * 64 * RPAD;    // layer1 weight chunk 1
    __nv_bfloat16* As  = smh + 3 * 64 * RPAD;    // activation staging

    const int t    = threadIdx.x;
    const int ks   = blockIdx.x & 7;
    const int cg   = blockIdx.x >> 3;
    const int warp = t >> 5, lane = t & 31;
    const int mt   = warp & 3;       // m16 tile (4 x 16 = 64 batch rows)
    const int nh   = warp >> 2;      // 16-col strip (4 x 16 = 64 cols)

    // resident weight slices
    for (int i = t; i < 64 * 48; i += RTHREADS) {
        int c = i / 48, f = i % 48;
        *(uint4*)(B0s + c * RPAD + f * 8) =
            *(const uint4*)(Wh0p + (size_t)(cg * 64 + c) * K3 + ks * RKS + f * 8);
    }
    {
        const __nv_bfloat16* Wsrc = (ks < 4) ? W1p : Wh1p;
        const int colbase = (ks & 3) * RKS2;
        for (int i = t; i < 64 * 48; i += RTHREADS) {
            int c = i / 48, f = i % 48;
            *(uint4*)(B1a + c * RPAD + f * 8) =
                *(const uint4*)(Wsrc + (size_t)(cg * 64 + c) * K3 + colbase + f * 8);
            *(uint4*)(B1b + c * RPAD + f * 8) =
                *(const uint4*)(Wsrc + (size_t)(cg * 64 + c) * K3 + colbase + RKS + f * 8);
        }
    }

    const int arow = mt * 16 + (lane >> 2);
    const int kq   = (lane & 3) * 2;
    const int crow = nh * 16 + (lane >> 2);

    for (int w = 0; w <= SQ; w++) {
        float acc0[2][4], acc1[2][4];

        // ---- phase A: layer0 step w ----
        if (w < SQ) {
            const __nv_bfloat16* Ain = Hp0 + (size_t)w * (BA * K3) + ks * RKS;
            __syncthreads();
            for (int i = t; i < 64 * 48; i += RTHREADS) {
                int b = i / 48, f = i % 48;
                *(uint4*)(As + b * RPAD + f * 8) = *(const uint4*)(Ain + (size_t)b * K3 + f * 8);
            }
            __syncthreads();

            #pragma unroll
            for (int nt = 0; nt < 2; nt++)
                #pragma unroll
                for (int j = 0; j < 4; j++) acc0[nt][j] = 0.f;
            mma_block512(As, B0s, arow, kq, crow, acc0);

            float* pp = g_part0 + (size_t)ks * BA * HID + (size_t)cg * 64;
            int r = lane >> 2, cq = (lane & 3) * 2;
            #pragma unroll
            for (int nt = 0; nt < 2; nt++) {
                int c = nh * 16 + nt * 8 + cq;
                *(float2*)(pp + (size_t)(mt * 16 + r)     * HID + c) = make_float2(acc0[nt][0], acc0[nt][1]);
                *(float2*)(pp + (size_t)(mt * 16 + r + 8) * HID + c) = make_float2(acc0[nt][2], acc0[nt][3]);
            }
        }

        // ---- phase B: layer1 step w-1 (K-concat folds P1) ----
        if (w >= 1) {
            const __nv_bfloat16* src = (ks < 4)
                ? (Hp0 + (size_t)w       * (BA * K3) + ks * RKS2)
                : (Hp1 + (size_t)(w - 1) * (BA * K3) + (ks - 4) * RKS2);

            #pragma unroll
            for (int nt = 0; nt < 2; nt++)
                #pragma unroll
                for (int j = 0; j < 4; j++) acc1[nt][j] = 0.f;

            #pragma unroll
            for (int ch = 0; ch < 2; ch++) {
                __syncthreads();
                for (int i = t; i < 64 * 48; i += RTHREADS) {
                    int b = i / 48, f = i % 48;
                    *(uint4*)(As + b * RPAD + f * 8) =
                        *(const uint4*)(src + (size_t)b * K3 + ch * RKS + f * 8);
                }
                __syncthreads();
                mma_block512(As, ch ? B1b : B1a, arow, kq, crow, acc1);
            }

            float* pp = g_part1 + (size_t)ks * BA * HID + (size_t)cg * 64;
            int r = lane >> 2, cq = (lane & 3) * 2;
            #pragma unroll
            for (int nt = 0; nt < 2; nt++) {
                int c = nh * 16 + nt * 8 + cq;
                *(float2*)(pp + (size_t)(mt * 16 + r)     * HID + c) = make_float2(acc1[nt][0], acc1[nt][1]);
                *(float2*)(pp + (size_t)(mt * 16 + r + 8) * HID + c) = make_float2(acc1[nt][2], acc1[nt][3]);
            }
        }

        gbar();

        // ---- reduce + tanh + pack (one iteration: 512 outputs / 512 threads) ----
        if (w < SQ) {
            __nv_bfloat16* Hout = Hp0 + (size_t)(w + 1) * (BA * K3);
            const float* Pt = P0 + (size_t)w * BH;
            int o = blockIdx.x * 512 + t;
            int b = o >> 10, c = o & 1023;
            float s = 0.f;
            #pragma unroll
            for (int k2 = 0; k2 < 8; k2++)
                s += g_part0[(size_t)k2 * BA * HID + o];
            float h = tanhf(s + Pt[o] + bias0[c]);
            __nv_bfloat16 hi = __float2bfloat16(h);
            __nv_bfloat16 lo = __float2bfloat16(h - __bfloat162float(hi));
            __nv_bfloat16* dr = Hout + (size_t)b * K3;
            dr[c]           = hi;
            dr[HID + c]     = hi;
            dr[2 * HID + c] = lo;
            if (w == SQ - 1) Hl0[o] = h;
        }
        if (w >= 1) {
            __nv_bfloat16* Hout = Hp1 + (size_t)w * (BA * K3);
            int o = blockIdx.x * 512 + t;
            int b = o >> 10, c = o & 1023;
            float s = 0.f;
            #pragma unroll
            for (int k2 = 0; k2 < 8; k2++)
                s += g_part1[(size_t)k2 * BA * HID + o];
            float h = tanhf(s + bias1[c]);
            __nv_bfloat16 hi = __float2bfloat16(h);
            __nv_bfloat16 lo = __float2bfloat16(h - __bfloat162float(hi));
            __nv_bfloat16* dr = Hout + (size_t)b * K3;
            dr[c]           = hi;
            dr[HID + c]     = hi;
            dr[2 * HID + c] = lo;
            if (w == SQ) Hl1[o] = h;
        }
        gbar();
    }
}

__global__ void write_hidden(const float* __restrict__ h0, const float* __restrict__ h1,
                             float* __restrict__ dst)
{
    int i = blockIdx.x * 256 + threadIdx.x;
    if (i < BH) {
        dst[i]      = h0[i];
        dst[BH + i] = h1[i];
    }
}

extern "C" void kernel_launch(void* const* d_in, const int* in_sizes, int n_in,
                              void* d_out, int out_size)
{
    const int*   inputs = (const int*)  d_in[0];
    const float* hidden = (const float*)d_in[1];
    const float* emb    = (const float*)d_in[2];
    const float* W0     = (const float*)d_in[3];
    const float* Wh0    = (const float*)d_in[4];
    const float* b0     = (const float*)d_in[5];
    const float* W1     = (const float*)d_in[6];
    const float* Wh1    = (const float*)d_in[7];
    const float* b1     = (const float*)d_in[8];
    const float* Wd     = (const float*)d_in[9];
    const float* bd     = (const float*)d_in[10];
    float* out = (float*)d_out;

    float *P0, *Hl0, *Hl1;
    cudaGetSymbolAddress((void**)&P0,  g_P0);
    cudaGetSymbolAddress((void**)&Hl0, g_Hlast0);
    cudaGetSymbolAddress((void**)&Hl1, g_Hlast1);
    __nv_bfloat16 *A3, *W03, *W13, *Wd3, *Wh03, *Wh13, *Hp0, *Hp1;
    cudaGetSymbolAddress((void**)&A3,   g_A3);
    cudaGetSymbolAddress((void**)&W03,  g_W03);
    cudaGetSymbolAddress((void**)&W13,  g_W13);
    cudaGetSymbolAddress((void**)&Wd3,  g_Wd3);
    cudaGetSymbolAddress((void**)&Wh03, g_Wh03);
    cudaGetSymbolAddress((void**)&Wh13, g_Wh13);
    cudaGetSymbolAddress((void**)&Hp0,  g_Hp0);
    cudaGetSymbolAddress((void**)&Hp1,  g_Hp1);

    static bool attr_set = false;
    const int rec_smem = 4 * 64 * RPAD * 2;   // 200704 B
    if (!attr_set) {
        cudaFuncSetAttribute(rnn_fused,
                             cudaFuncAttributeMaxDynamicSharedMemorySize, rec_smem);
        attr_set = true;
    }

    const int PK = HID / 4;

    // pack weights (B-order)
    pack_split<false, false><<<(HID * PK + 255) / 256, 256>>>(W0,  nullptr, W03,  HID);
    pack_split<false, false><<<(HID * PK + 255) / 256, 256>>>(W1,  nullptr, W13,  HID);
    pack_split<false, false><<<(VOC * PK + 255) / 256, 256>>>(Wd,  nullptr, Wd3,  VOC);
    pack_split<false, false><<<(HID * PK + 255) / 256, 256>>>(Wh0, nullptr, Wh03, HID);
    pack_split<false, false><<<(HID * PK + 255) / 256, 256>>>(Wh1, nullptr, Wh13, HID);

    // initial hidden -> packed chain slot 0 (A-order)
    pack_split<false, true><<<(BA * PK + 255) / 256, 256>>>(hidden,      nullptr, Hp0, BA);
    pack_split<false, true><<<(BA * PK + 255) / 256, 256>>>(hidden + BH, nullptr, Hp1, BA);

    // K1: P0 = emb[inputs] @ W0^T
    pack_split<true, true><<<(MROWS * PK + 255) / 256, 256>>>(emb, inputs, A3, MROWS);
    gemm_bf16<false, false><<<dim3(MROWS / 128, HID / 128), 256>>>(A3, W03, nullptr, P0, HID);

    // fused 2-layer wavefront recurrence (folds the H0@W1^T GEMM)
    rnn_fused<<<NCTA, RTHREADS, rec_smem>>>(Wh03, W13, Wh13, P0, b0, b1, Hp0, Hp1, Hl0, Hl1);

    // decoder: logits = H1 @ Wd^T + bd
    gemm_bf16<true, true><<<dim3(MROWS / 128, (VOC + 127) / 128), 256>>>(
        Hp1 + (size_t)BA * K3, Wd3, bd, out, VOC);

    // hidden_final
    if (out_size >= MROWS * VOC + 2 * BH)
        write_hidden<<<(BH + 255) / 256, 256>>>(Hl0, Hl1, out + (size_t)MROWS * VOC);
}

// round 16
// speedup vs baseline: 1.0951x; 1.0951x over previous
#include <cuda_runtime.h>
#include <cuda_bf16.h>
#include <stdint.h>
#include <math.h>

#define SQ   64
#define BA   64
#define HID  1024
#define EMBD 1024
#define VOC  10000
#define BH   (BA*HID)
#define MROWS (SQ*BA)   // 4096
#define K3   (3*HID)    // 3072 split-bf16 K

#define NCTA 128
#define RKS  384        // layer0 k3 per slice (3072/8)
#define RKS2 768        // layer1 k6144 per slice (6144/8)
#define RPAD 392        // padded smem row stride (halves)

// ---- scratch (device globals) ----
__device__ float g_P0[MROWS*HID];
__device__ float g_part0[8*BA*HID];
__device__ float g_part1[8*BA*HID];
__device__ float g_Hlast0[BH];
__device__ float g_Hlast1[BH];

__device__ __nv_bfloat16 g_A3  [MROWS*K3];      // packed A for K1 (emb gather)
__device__ __nv_bfloat16 g_W03 [HID*K3];        // packed weights (B-order hi|lo|hi)
__device__ __nv_bfloat16 g_W13 [HID*K3];
__device__ __nv_bfloat16 g_Wd3 [VOC*K3];
__device__ __nv_bfloat16 g_Wh03[HID*K3];
__device__ __nv_bfloat16 g_Wh13[HID*K3];
__device__ __nv_bfloat16 g_Hp0 [(SQ+1)*BA*K3];  // packed hidden chains (A-order)
__device__ __nv_bfloat16 g_Hp1 [(SQ+1)*BA*K3];

// ---- hierarchical grid barrier (monotone counters, wrap-safe) ----
__device__ unsigned g_leaf[8 * 32];
__device__ unsigned g_root;
__device__ volatile unsigned g_gen;

__device__ __forceinline__ void gbar()
{
    __syncthreads();
    if (threadIdx.x == 0) {
        __threadfence();
        unsigned my = g_gen;
        const int leaf = (blockIdx.x & 7) * 32;
        if ((atomicAdd(&g_leaf[leaf], 1u) & 15u) == 15u) {
            if ((atomicAdd(&g_root, 1u) & 7u) == 7u) {
                __threadfence();
                g_gen = my + 1;
            }
        }
        while (g_gen == my) { }
        __threadfence();
    }
    __syncthreads();
}

// ---------------------------------------------------------------------------
// Split-pack: fp32 [R,HID] -> bf16 [R,3*HID].
// A-order (AORD=1): [hi|hi|lo].  B-order (AORD=0): [hi|lo|hi].
// ---------------------------------------------------------------------------
template<bool GATHER, bool AORD>
__global__ __launch_bounds__(256)
void pack_split(const float* __restrict__ src, const int* __restrict__ idx,
                __nv_bfloat16* __restrict__ dst, int R)
{
    long i = (long)blockIdx.x * 256 + threadIdx.x;
    if (i >= (long)R * (HID / 4)) return;
    int r  = (int)(i / (HID / 4));
    int k4 = (int)(i % (HID / 4)) * 4;
    const float* row = GATHER ? (src + (size_t)idx[r] * HID)
                              : (src + (size_t)r * HID);
    float4 v = *(const float4*)(row + k4);

    __nv_bfloat16 h[4], l[4];
    float f[4] = {v.x, v.y, v.z, v.w};
    #pragma unroll
    for (int j = 0; j < 4; j++) {
        h[j] = __float2bfloat16(f[j]);
        l[j] = __float2bfloat16(f[j] - __bfloat162float(h[j]));
    }
    __nv_bfloat16* d = dst + (size_t)r * K3;
    *(uint2*)(d + k4)                        = *(uint2*)h;
    *(uint2*)(d + (AORD ? HID : 2*HID) + k4) = *(uint2*)h;
    *(uint2*)(d + (AORD ? 2*HID : HID) + k4) = *(uint2*)l;
}

__device__ __forceinline__ void mma16816(float* c, const uint32_t* a, const uint32_t* b)
{
    asm volatile(
        "mma.sync.aligned.m16n8k16.row.col.f32.bf16.bf16.f32 "
        "{%0,%1,%2,%3}, {%4,%5,%6,%7}, {%8,%9}, {%0,%1,%2,%3};"
        : "+f"(c[0]), "+f"(c[1]), "+f"(c[2]), "+f"(c[3])
        : "r"(a[0]), "r"(a[1]), "r"(a[2]), "r"(a[3]), "r"(b[0]), "r"(b[1]));
}

__device__ __forceinline__ void ldsm_x4(uint32_t* r, uint32_t addr)
{
    asm volatile("ldmatrix.sync.aligned.m8n8.x4.shared.b16 {%0,%1,%2,%3}, [%4];"
        : "=r"(r[0]), "=r"(r[1]), "=r"(r[2]), "=r"(r[3]) : "r"(addr));
}

// ---------------------------------------------------------------------------
// bf16 tensor-core GEMM (mma.sync + ldmatrix): C = A[M,K3] @ B[N,K3]^T (+bias)
// CTA 128x128, K-tile 32, 256 threads (8 warps: 4m x 2n), double-buffered.
// Fragment loads via ldmatrix.x4: 6 LDSM per k16 step (was 24 scalar LDS.32).
// ---------------------------------------------------------------------------
#define SMP 40

template<bool BIAS, bool GUARD>
__global__ __launch_bounds__(256, 2)
void gemm_bf16(const __nv_bfloat16* __restrict__ A, const __nv_bfloat16* __restrict__ B,
               const float* __restrict__ bias, float* __restrict__ C, int N)
{
    __shared__ __nv_bfloat16 As[2][128 * SMP];
    __shared__ __nv_bfloat16 Bs[2][128 * SMP];

    const int t    = threadIdx.x;
    const int warp = t >> 5, lane = t & 31;
    const int mBase = blockIdx.x * 128;
    const int nBase = blockIdx.y * 128;
    const int warpM = (warp >> 1) * 32;
    const int warpN = (warp & 1) * 64;

    const int lr = t >> 1;
    const int lk = (t & 1) * 16;

    const __nv_bfloat16* Ag = A + (size_t)(mBase + lr) * K3 + lk;
    int gn = nBase + lr;
    bool bvalid = true;
    if (GUARD && gn >= N) { bvalid = false; gn = N - 1; }
    const __nv_bfloat16* Bg = B + (size_t)gn * K3 + lk;

    uint4 av0 = *(const uint4*)(Ag);
    uint4 av1 = *(const uint4*)(Ag + 8);
    uint4 bv0 = make_uint4(0,0,0,0), bv1 = make_uint4(0,0,0,0);
    if (!GUARD || bvalid) { bv0 = *(const uint4*)(Bg); bv1 = *(const uint4*)(Bg + 8); }

    float acc[2][8][4];
    #pragma unroll
    for (int mi = 0; mi < 2; mi++)
        #pragma unroll
        for (int ni = 0; ni < 8; ni++)
            #pragma unroll
            for (int j = 0; j < 4; j++) acc[mi][ni][j] = 0.f;

    // ldmatrix address layout: lane groups of 8 supply rows of each 8x8 matrix.
    // matrix j: rows base + ((lane>>3)&1)*8 + (lane&7), k-col base + (lane>>4)*8
    const int ldrow = ((lane >> 3) & 1) * 8 + (lane & 7);
    const int ldcol = (lane >> 4) * 8;

    const uint32_t As0 = (uint32_t)__cvta_generic_to_shared(&As[0][0]);
    const uint32_t Bs0 = (uint32_t)__cvta_generic_to_shared(&Bs[0][0]);
    const uint32_t bufBytes = 128 * SMP * 2;

    uint32_t aoff[2], boff[4];
    #pragma unroll
    for (int mi = 0; mi < 2; mi++)
        aoff[mi] = ((warpM + mi * 16 + ldrow) * SMP + ldcol) * 2;
    #pragma unroll
    for (int p = 0; p < 4; p++)
        boff[p] = ((warpN + p * 16 + ldrow) * SMP + ldcol) * 2;

    int buf = 0;
    for (int kt = 0; kt < K3; kt += 32) {
        *(uint4*)&As[buf][lr * SMP + lk]     = av0;
        *(uint4*)&As[buf][lr * SMP + lk + 8] = av1;
        *(uint4*)&Bs[buf][lr * SMP + lk]     = bv0;
        *(uint4*)&Bs[buf][lr * SMP + lk + 8] = bv1;
        __syncthreads();

        if (kt + 32 < K3) {
            av0 = *(const uint4*)(Ag + kt + 32);
            av1 = *(const uint4*)(Ag + kt + 40);
            if (!GUARD || bvalid) {
                bv0 = *(const uint4*)(Bg + kt + 32);
                bv1 = *(const uint4*)(Bg + kt + 40);
            }
        }

        const uint32_t aBuf = As0 + buf * bufBytes;
        const uint32_t bBuf = Bs0 + buf * bufBytes;

        #pragma unroll
        for (int ks = 0; ks < 2; ks++) {
            const uint32_t kk2 = ks * 32;     // k16 = 32 bytes
            uint32_t a[2][4], bq[4][4];
            #pragma unroll
            for (int mi = 0; mi < 2; mi++)
                ldsm_x4(a[mi], aBuf + aoff[mi] + kk2);
            #pragma unroll
            for (int p = 0; p < 4; p++)
                ldsm_x4(bq[p], bBuf + boff[p] + kk2);

            #pragma unroll
            for (int mi = 0; mi < 2; mi++)
                #pragma unroll
                for (int ni = 0; ni < 8; ni++) {
                    uint32_t bb[2] = { bq[ni >> 1][ni & 1], bq[ni >> 1][2 + (ni & 1)] };
                    mma16816(acc[mi][ni], a[mi], bb);
                }
        }
        buf ^= 1;
    }

    #pragma unroll
    for (int mi = 0; mi < 2; mi++) {
        int row = mBase + warpM + mi * 16 + (lane >> 2);
        #pragma unroll
        for (int ni = 0; ni < 8; ni++) {
            int col = nBase + warpN + ni * 8 + (lane & 3) * 2;
            if (!GUARD || col < N) {
                float bb0 = BIAS ? bias[col]     : 0.f;
                float bb1 = BIAS ? bias[col + 1] : 0.f;
                *(float2*)(C + (size_t)row * N + col) =
                    make_float2(acc[mi][ni][0] + bb0, acc[mi][ni][1] + bb1);
                *(float2*)(C + (size_t)(row + 8) * N + col) =
                    make_float2(acc[mi][ni][2] + bb0, acc[mi][ni][3] + bb1);
            }
        }
    }
}

// ---------------------------------------------------------------------------
// Fused 2-layer wavefront recurrence (R13 best config: 256 threads).
// 128 CTAs = 8 k-slices x 16 col-groups.
// Wave w: layer0 step w (if w<SQ) + layer1 step w-1 (if w>=1).
// ---------------------------------------------------------------------------
__device__ __forceinline__ void mma_block(const __nv_bfloat16* As, const __nv_bfloat16* Bs,
                                          int arow, int kq, int crow, float acc[4][4])
{
    #pragma unroll 2
    for (int k = 0; k < RKS; k += 16) {
        uint32_t a[4];
        a[0] = *(const uint32_t*)(As + (size_t) arow      * RPAD + k + kq);
        a[1] = *(const uint32_t*)(As + (size_t)(arow + 8) * RPAD + k + kq);
        a[2] = *(const uint32_t*)(As + (size_t) arow      * RPAD + k + kq + 8);
        a[3] = *(const uint32_t*)(As + (size_t)(arow + 8) * RPAD + k + kq + 8);
        #pragma unroll
        for (int nt = 0; nt < 4; nt++) {
            int c = crow + nt * 8;
            uint32_t b[2];
            b[0] = *(const uint32_t*)(Bs + (size_t)c * RPAD + k + kq);
            b[1] = *(const uint32_t*)(Bs + (size_t)c * RPAD + k + kq + 8);
            mma16816(acc[nt], a, b);
        }
    }
}

__global__ __launch_bounds__(256, 1)
void rnn_fused(const __nv_bfloat16* __restrict__ Wh0p,
               const __nv_bfloat16* __restrict__ W1p,
               const __nv_bfloat16* __restrict__ Wh1p,
               const float* __restrict__ P0,
               const float* __restrict__ bias0,
               const float* __restrict__ bias1,
               __nv_bfloat16* __restrict__ Hp0,
               __nv_bfloat16* __restrict__ Hp1,
               float* __restrict__ Hl0,
               float* __restrict__ Hl1)
{
    extern __shared__ __nv_bfloat16 smh[];
    __nv_bfloat16* B0s = smh;                    // layer0 weight slice
    __nv_bfloat16* B1a = smh + 64 * RPAD;        // layer1 weight chunk 0
    __nv_bfloat16* B1b = smh + 2 * 64 * RPAD;    // layer1 weight chunk 1
    __nv_bfloat16* As  = smh + 3 * 64 * RPAD;    // activation staging

    const int t    = threadIdx.x;
    const int ks   = blockIdx.x & 7;
    const int cg   = blockIdx.x >> 3;
    const int warp = t >> 5, lane = t & 31;
    const int mt   = warp & 3;
    const int nh   = warp >> 2;

    // resident weight slices
    for (int i = t; i < 64 * 48; i += 256) {
        int c = i / 48, f = i % 48;
        *(uint4*)(B0s + c * RPAD + f * 8) =
            *(const uint4*)(Wh0p + (size_t)(cg * 64 + c) * K3 + ks * RKS + f * 8);
    }
    {
        const __nv_bfloat16* Wsrc = (ks < 4) ? W1p : Wh1p;
        const int colbase = (ks & 3) * RKS2;
        for (int i = t; i < 64 * 48; i += 256) {
            int c = i / 48, f = i % 48;
            *(uint4*)(B1a + c * RPAD + f * 8) =
                *(const uint4*)(Wsrc + (size_t)(cg * 64 + c) * K3 + colbase + f * 8);
            *(uint4*)(B1b + c * RPAD + f * 8) =
                *(const uint4*)(Wsrc + (size_t)(cg * 64 + c) * K3 + colbase + RKS + f * 8);
        }
    }

    const int arow = mt * 16 + (lane >> 2);
    const int kq   = (lane & 3) * 2;
    const int crow = nh * 32 + (lane >> 2);

    for (int w = 0; w <= SQ; w++) {
        float acc0[4][4], acc1[4][4];

        // ---- phase A: layer0 step w ----
        if (w < SQ) {
            const __nv_bfloat16* Ain = Hp0 + (size_t)w * (BA * K3) + ks * RKS;
            __syncthreads();
            for (int i = t; i < 64 * 48; i += 256) {
                int b = i / 48, f = i % 48;
                *(uint4*)(As + b * RPAD + f * 8) = *(const uint4*)(Ain + (size_t)b * K3 + f * 8);
            }
            __syncthreads();

            #pragma unroll
            for (int nt = 0; nt < 4; nt++)
                #pragma unroll
                for (int j = 0; j < 4; j++) acc0[nt][j] = 0.f;
            mma_block(As, B0s, arow, kq, crow, acc0);

            float* pp = g_part0 + (size_t)ks * BA * HID + (size_t)cg * 64;
            int r = lane >> 2, cq = (lane & 3) * 2;
            #pragma unroll
            for (int nt = 0; nt < 4; nt++) {
                int c = nh * 32 + nt * 8 + cq;
                *(float2*)(pp + (size_t)(mt * 16 + r)     * HID + c) = make_float2(acc0[nt][0], acc0[nt][1]);
                *(float2*)(pp + (size_t)(mt * 16 + r + 8) * HID + c) = make_float2(acc0[nt][2], acc0[nt][3]);
            }
        }

        // ---- phase B: layer1 step w-1 (K-concat folds P1) ----
        if (w >= 1) {
            const __nv_bfloat16* src = (ks < 4)
                ? (Hp0 + (size_t)w       * (BA * K3) + ks * RKS2)
                : (Hp1 + (size_t)(w - 1) * (BA * K3) + (ks - 4) * RKS2);

            #pragma unroll
            for (int nt = 0; nt < 4; nt++)
                #pragma unroll
                for (int j = 0; j < 4; j++) acc1[nt][j] = 0.f;

            #pragma unroll
            for (int ch = 0; ch < 2; ch++) {
                __syncthreads();
                for (int i = t; i < 64 * 48; i += 256) {
                    int b = i / 48, f = i % 48;
                    *(uint4*)(As + b * RPAD + f * 8) =
                        *(const uint4*)(src + (size_t)b * K3 + ch * RKS + f * 8);
                }
                __syncthreads();
                mma_block(As, ch ? B1b : B1a, arow, kq, crow, acc1);
            }

            float* pp = g_part1 + (size_t)ks * BA * HID + (size_t)cg * 64;
            int r = lane >> 2, cq = (lane & 3) * 2;
            #pragma unroll
            for (int nt = 0; nt < 4; nt++) {
                int c = nh * 32 + nt * 8 + cq;
                *(float2*)(pp + (size_t)(mt * 16 + r)     * HID + c) = make_float2(acc1[nt][0], acc1[nt][1]);
                *(float2*)(pp + (size_t)(mt * 16 + r + 8) * HID + c) = make_float2(acc1[nt][2], acc1[nt][3]);
            }
        }

        gbar();

        // ---- reduce + tanh + pack ----
        if (w < SQ) {
            __nv_bfloat16* Hout = Hp0 + (size_t)(w + 1) * (BA * K3);
            const float* Pt = P0 + (size_t)w * BH;
            int base = blockIdx.x * 512;
            #pragma unroll
            for (int r2 = 0; r2 < 2; r2++) {
                int o = base + r2 * 256 + t;
                int b = o >> 10, c = o & 1023;
                float s = 0.f;
                #pragma unroll
                for (int k2 = 0; k2 < 8; k2++)
                    s += g_part0[(size_t)k2 * BA * HID + o];
                float h = tanhf(s + Pt[o] + bias0[c]);
                __nv_bfloat16 hi = __float2bfloat16(h);
                __nv_bfloat16 lo = __float2bfloat16(h - __bfloat162float(hi));
                __nv_bfloat16* dr = Hout + (size_t)b * K3;
                dr[c]           = hi;
                dr[HID + c]     = hi;
                dr[2 * HID + c] = lo;
                if (w == SQ - 1) Hl0[o] = h;
            }
        }
        if (w >= 1) {
            __nv_bfloat16* Hout = Hp1 + (size_t)w * (BA * K3);
            int base = blockIdx.x * 512;
            #pragma unroll
            for (int r2 = 0; r2 < 2; r2++) {
                int o = base + r2 * 256 + t;
                int b = o >> 10, c = o & 1023;
                float s = 0.f;
                #pragma unroll
                for (int k2 = 0; k2 < 8; k2++)
                    s += g_part1[(size_t)k2 * BA * HID + o];
                float h = tanhf(s + bias1[c]);
                __nv_bfloat16 hi = __float2bfloat16(h);
                __nv_bfloat16 lo = __float2bfloat16(h - __bfloat162float(hi));
                __nv_bfloat16* dr = Hout + (size_t)b * K3;
                dr[c]           = hi;
                dr[HID + c]     = hi;
                dr[2 * HID + c] = lo;
                if (w == SQ) Hl1[o] = h;
            }
        }
        gbar();
    }
}

__global__ void write_hidden(const float* __restrict__ h0, const float* __restrict__ h1,
                             float* __restrict__ dst)
{
    int i = blockIdx.x * 256 + threadIdx.x;
    if (i < BH) {
        dst[i]      = h0[i];
        dst[BH + i] = h1[i];
    }
}

extern "C" void kernel_launch(void* const* d_in, const int* in_sizes, int n_in,
                              void* d_out, int out_size)
{
    const int*   inputs = (const int*)  d_in[0];
    const float* hidden = (const float*)d_in[1];
    const float* emb    = (const float*)d_in[2];
    const float* W0     = (const float*)d_in[3];
    const float* Wh0    = (const float*)d_in[4];
    const float* b0     = (const float*)d_in[5];
    const float* W1     = (const float*)d_in[6];
    const float* Wh1    = (const float*)d_in[7];
    const float* b1     = (const float*)d_in[8];
    const float* Wd     = (const float*)d_in[9];
    const float* bd     = (const float*)d_in[10];
    float* out = (float*)d_out;

    float *P0, *Hl0, *Hl1;
    cudaGetSymbolAddress((void**)&P0,  g_P0);
    cudaGetSymbolAddress((void**)&Hl0, g_Hlast0);
    cudaGetSymbolAddress((void**)&Hl1, g_Hlast1);
    __nv_bfloat16 *A3, *W03, *W13, *Wd3, *Wh03, *Wh13, *Hp0, *Hp1;
    cudaGetSymbolAddress((void**)&A3,   g_A3);
    cudaGetSymbolAddress((void**)&W03,  g_W03);
    cudaGetSymbolAddress((void**)&W13,  g_W13);
    cudaGetSymbolAddress((void**)&Wd3,  g_Wd3);
    cudaGetSymbolAddress((void**)&Wh03, g_Wh03);
    cudaGetSymbolAddress((void**)&Wh13, g_Wh13);
    cudaGetSymbolAddress((void**)&Hp0,  g_Hp0);
    cudaGetSymbolAddress((void**)&Hp1,  g_Hp1);

    static bool attr_set = false;
    const int rec_smem = 4 * 64 * RPAD * 2;   // 200704 B
    if (!attr_set) {
        cudaFuncSetAttribute(rnn_fused,
                             cudaFuncAttributeMaxDynamicSharedMemorySize, rec_smem);
        attr_set = true;
    }

    const int PK = HID / 4;

    // pack weights (B-order)
    pack_split<false, false><<<(HID * PK + 255) / 256, 256>>>(W0,  nullptr, W03,  HID);
    pack_split<false, false><<<(HID * PK + 255) / 256, 256>>>(W1,  nullptr, W13,  HID);
    pack_split<false, false><<<(VOC * PK + 255) / 256, 256>>>(Wd,  nullptr, Wd3,  VOC);
    pack_split<false, false><<<(HID * PK + 255) / 256, 256>>>(Wh0, nullptr, Wh03, HID);
    pack_split<false, false><<<(HID * PK + 255) / 256, 256>>>(Wh1, nullptr, Wh13, HID);

    // initial hidden -> packed chain slot 0 (A-order)
    pack_split<false, true><<<(BA * PK + 255) / 256, 256>>>(hidden,      nullptr, Hp0, BA);
    pack_split<false, true><<<(BA * PK + 255) / 256, 256>>>(hidden + BH, nullptr, Hp1, BA);

    // K1: P0 = emb[inputs] @ W0^T
    pack_split<true, true><<<(MROWS * PK + 255) / 256, 256>>>(emb, inputs, A3, MROWS);
    gemm_bf16<false, false><<<dim3(MROWS / 128, HID / 128), 256>>>(A3, W03, nullptr, P0, HID);

    // fused 2-layer wavefront recurrence (folds the H0@W1^T GEMM)
    rnn_fused<<<NCTA, 256, rec_smem>>>(Wh03, W13, Wh13, P0, b0, b1, Hp0, Hp1, Hl0, Hl1);

    // decoder: logits = H1 @ Wd^T + bd
    gemm_bf16<true, true><<<dim3(MROWS / 128, (VOC + 127) / 128), 256>>>(
        Hp1 + (size_t)BA * K3, Wd3, bd, out, VOC);

    // hidden_final
    if (out_size >= MROWS * VOC + 2 * BH)
        write_hidden<<<(BH + 255) / 256, 256>>>(Hl0, Hl1, out + (size_t)MROWS * VOC);
}